// round 14
// baseline (speedup 1.0000x reference)
#include <cuda_runtime.h>
#include <cuda_bf16.h>
#include <math_constants.h>

// GeomAttention: B=2, L=S=2048, H=8, E=D=32, fp32.
// Cauchy-Schwarz => relu never fires: score = c*(dot+dot^2) - c*qn2*kn2.
// Shift softmax (log2): C2 = min(c2*qn2*KMIN, 100), p = 2^(score2 + C2).
//
// R13: R12 with the missing uint32_t type fixed (unsigned int). R9's exact
// geometry (64-thread blocks, 2 rows/thread, chunk-8, SPLITS=2) + cp.async
// double-buffered K/V tiles, split-wide kn2 preload, log2 ex2, packed fadd2
// dot reduce. Fused last-block merge unchanged.

static constexpr int B_ = 2, L_ = 2048, H_ = 8, E_ = 32;
static constexpr int SPLITS = 2;
static constexpr int SKEYS  = L_ / SPLITS;   // 1024
static constexpr int TS = 64;                // keys per SMEM tile
static constexpr int NT = SKEYS / TS;        // 16 tiles
static constexpr int CH = 8;                 // keys per score chunk
static constexpr int THREADS = 64;           // 2 warps
static constexpr int ROWSPB = 2 * THREADS;   // 128 rows per block
static constexpr int NR = B_ * L_ * H_;      // 32768 rows
static constexpr int NGROUPS = (L_ / ROWSPB) * H_ * B_;  // 256

__device__ float  g_l[SPLITS * NR];
__device__ float4 g_acc[SPLITS * NR * 8];
__device__ float  g_kmin[B_ * H_];
__device__ float  g_kn2[B_ * H_ * L_];       // [(b*H+h)*L + s]
__device__ int    g_cnt[NGROUPS];            // zero-init; self-resetting

typedef unsigned long long u64;
typedef unsigned int u32;

__device__ __forceinline__ u64 pk2(float a, float b) {
    u64 r; asm("mov.b64 %0, {%1,%2};" : "=l"(r) : "f"(a), "f"(b)); return r;
}
__device__ __forceinline__ float2 upk2(u64 v) {
    float2 r; asm("mov.b64 {%0,%1}, %2;" : "=f"(r.x), "=f"(r.y) : "l"(v)); return r;
}
__device__ __forceinline__ u64 ffma2(u64 a, u64 b, u64 c) {
    u64 d; asm("fma.rn.f32x2 %0, %1, %2, %3;" : "=l"(d) : "l"(a), "l"(b), "l"(c)); return d;
}
__device__ __forceinline__ u64 fadd2(u64 a, u64 b) {
    u64 d; asm("add.rn.f32x2 %0, %1, %2;" : "=l"(d) : "l"(a), "l"(b)); return d;
}
__device__ __forceinline__ float ex2f(float x) {
    float r; asm("ex2.approx.f32 %0, %1;" : "=f"(r) : "f"(x)); return r;
}
__device__ __forceinline__ u32 s2u(const void* p) {
    return (u32)__cvta_generic_to_shared(p);
}
__device__ __forceinline__ void cpa16(u32 dst, const void* src) {
    asm volatile("cp.async.cg.shared.global [%0], [%1], 16;" :: "r"(dst), "l"(src));
}
__device__ __forceinline__ void cpa4(u32 dst, const void* src) {
    asm volatile("cp.async.ca.shared.global [%0], [%1], 4;" :: "r"(dst), "l"(src));
}
#define CPA_COMMIT() asm volatile("cp.async.commit_group;" ::: "memory")
#define CPA_WAIT(n)  asm volatile("cp.async.wait_group %0;" :: "n"(n) : "memory")

// ---- pre-kernel: per-key |k|^2 and per-(b,h) min ----
__global__ __launch_bounds__(256) void kprep_kernel(const float* __restrict__ K)
{
    const int bh = blockIdx.x;               // 0..B*H-1
    const int b = bh / H_, h = bh % H_;
    const float* kbase = K + (((size_t)b * L_) * H_ + h) * E_;
    float mn = CUDART_INF_F;
    for (int s = threadIdx.x; s < L_; s += 256) {
        const float4* kp = (const float4*)(kbase + (size_t)s * (H_ * E_));
        float kn = 0.f;
        #pragma unroll
        for (int j = 0; j < 8; j++) {
            float4 v = kp[j];
            kn += v.x*v.x + v.y*v.y + v.z*v.z + v.w*v.w;
        }
        g_kn2[(size_t)bh * L_ + s] = kn;
        mn = fminf(mn, kn);
    }
    #pragma unroll
    for (int o = 16; o; o >>= 1) mn = fminf(mn, __shfl_xor_sync(0xffffffffu, mn, o));
    __shared__ float red[8];
    if ((threadIdx.x & 31) == 0) red[threadIdx.x >> 5] = mn;
    __syncthreads();
    if (threadIdx.x == 0) {
        float r = red[0];
        #pragma unroll
        for (int w = 1; w < 8; w++) r = fminf(r, red[w]);
        g_kmin[bh] = r;
    }
}

__global__ __launch_bounds__(THREADS, 4) void geom_attn_fused(
    const float* __restrict__ Q, const float* __restrict__ K,
    const float* __restrict__ V, float* __restrict__ O)
{
    __shared__ float4 sK[2][TS * 8];   // 2 x 8 KB
    __shared__ float4 sV[2][TS * 8];   // 2 x 8 KB
    __shared__ float  sKn2[SKEYS];     // 4 KB (whole split)
    __shared__ int    sLast;

    const int tid   = threadIdx.x;
    const int h     = blockIdx.y;
    const int bz    = blockIdx.z;
    const int b     = bz >> 1;                 // SPLITS == 2
    const int split = bz & 1;
    const int lbase = blockIdx.x * ROWSPB;
    const int l0    = lbase + tid;
    const int l1    = l0 + THREADS;
    const int bh    = b * H_ + h;

    const int key0 = split * SKEYS;
    const float* kbase = K + (((size_t)b * L_) * H_ + h) * E_;
    const float* vbase = V + (((size_t)b * L_) * H_ + h) * E_;
    const float* knb   = &g_kn2[(size_t)bh * L_ + key0];

    // ---- prologue: async-load kn2 for the whole split + tile 0 ----
    #pragma unroll
    for (int i = tid; i < SKEYS; i += THREADS)
        cpa4(s2u(&sKn2[i]), &knb[i]);
    #pragma unroll
    for (int i = tid; i < TS * 8; i += THREADS) {
        int r = i >> 3, j = i & 7;
        size_t off = (size_t)(key0 + r) * (H_ * E_) + j * 4;
        cpa16(s2u(&sK[0][i]), kbase + off);
        cpa16(s2u(&sV[0][i]), vbase + off);
    }
    CPA_COMMIT();

    // ---- load 2 query rows; |q|^2 each (overlaps with cp.async) ----
    const float* qp0 = Q + (((size_t)b * L_ + l0) * H_ + h) * E_;
    const float* qp1 = Q + (((size_t)b * L_ + l1) * H_ + h) * E_;
    u64 qa[16], qb[16];
    float qn2a = 0.f, qn2b = 0.f;
    #pragma unroll
    for (int j = 0; j < 8; j++) {
        float4 t = ((const float4*)qp0)[j];
        qa[2*j] = pk2(t.x, t.y); qa[2*j+1] = pk2(t.z, t.w);
        qn2a += t.x*t.x + t.y*t.y + t.z*t.z + t.w*t.w;
        float4 u = ((const float4*)qp1)[j];
        qb[2*j] = pk2(u.x, u.y); qb[2*j+1] = pk2(u.z, u.w);
        qn2b += u.x*u.x + u.y*u.y + u.z*u.z + u.w*u.w;
    }

    // log2-domain: p = 2^(c2*(dot+dot^2) - c2*qn2*kn2 + C2)
    const float c2  = 0.5f * rsqrtf((float)E_) * 1.4426950408889634f;
    const float cqa = c2 * qn2a, cqb = c2 * qn2b;
    const float km  = g_kmin[bh];
    const float Ca  = fminf(cqa * km, 100.f);  // safe fixed shift (log2)
    const float Cb  = fminf(cqb * km, 100.f);

    float ls0 = 0.f, ls1 = 0.f;
    u64 acca[16], accb[16];
    #pragma unroll
    for (int j = 0; j < 16; j++) { acca[j] = 0ull; accb[j] = 0ull; }

    for (int t = 0; t < NT; t++) {
        const int buf = t & 1;
        __syncthreads();                       // all warps done with buf^1
        if (t + 1 < NT) {                      // prefetch next tile
            #pragma unroll
            for (int i = tid; i < TS * 8; i += THREADS) {
                int r = i >> 3, j = i & 7;
                size_t off = (size_t)(key0 + (t + 1) * TS + r) * (H_ * E_) + j * 4;
                cpa16(s2u(&sK[buf ^ 1][i]), kbase + off);
                cpa16(s2u(&sV[buf ^ 1][i]), vbase + off);
            }
            CPA_COMMIT();
            CPA_WAIT(1);                       // tile t (older group) complete
        } else {
            CPA_WAIT(0);
        }
        __syncthreads();                       // cp.async data visible to all

        const int kofs = t * TS;
        for (int c0 = 0; c0 < TS; c0 += CH) {
            float sa[CH], sb[CH];
            // ---- phase 1: scores for CH keys x 2 rows ----
            #pragma unroll
            for (int u = 0; u < CH; u++) {
                const ulonglong2* kp = (const ulonglong2*)&sK[buf][(c0 + u) * 8];
                u64 a0 = 0ull, a1 = 0ull, b0 = 0ull, b1 = 0ull;
                #pragma unroll
                for (int j = 0; j < 8; j++) {
                    ulonglong2 kk = kp[j];          // broadcast across warp
                    a0 = ffma2(qa[2*j],   kk.x, a0);
                    a1 = ffma2(qa[2*j+1], kk.y, a1);
                    b0 = ffma2(qb[2*j],   kk.x, b0);
                    b1 = ffma2(qb[2*j+1], kk.y, b1);
                }
                float2 ra = upk2(fadd2(a0, a1));
                float2 rb = upk2(fadd2(b0, b1));
                float dota = ra.x + ra.y;
                float dotb = rb.x + rb.y;
                float kn2  = sKn2[kofs + c0 + u];
                float ta = fmaf(dota, dota, dota);   // dot + dot^2
                float tb = fmaf(dotb, dotb, dotb);
                sa[u] = fmaf(c2, ta, fmaf(-cqa, kn2, Ca));
                sb[u] = fmaf(c2, tb, fmaf(-cqb, kn2, Cb));
            }
            // ---- phase 2: exp2 + PV accumulate (straight-line) ----
            #pragma unroll
            for (int u = 0; u < CH; u++) {
                float pa = ex2f(sa[u]);
                float pb = ex2f(sb[u]);
                ls0 += pa; ls1 += pb;
                u64 ppa = pk2(pa, pa), ppb = pk2(pb, pb);
                const ulonglong2* vp = (const ulonglong2*)&sV[buf][(c0 + u) * 8];
                #pragma unroll
                for (int j = 0; j < 8; j++) {
                    ulonglong2 vv = vp[j];
                    acca[2*j]   = ffma2(ppa, vv.x, acca[2*j]);
                    acca[2*j+1] = ffma2(ppa, vv.y, acca[2*j+1]);
                    accb[2*j]   = ffma2(ppb, vv.x, accb[2*j]);
                    accb[2*j+1] = ffma2(ppb, vv.y, accb[2*j+1]);
                }
            }
        }
    }

    // ---- write partials ----
    const int r0 = ((b * L_ + l0) * H_ + h);
    const int r1 = ((b * L_ + l1) * H_ + h);
    g_l[split * NR + r0] = ls0;
    g_l[split * NR + r1] = ls1;
    float4* pa4 = &g_acc[(size_t)(split * NR + r0) * 8];
    float4* pb4 = &g_acc[(size_t)(split * NR + r1) * 8];
    #pragma unroll
    for (int j = 0; j < 8; j++) {
        float2 x = upk2(acca[2*j]), y = upk2(acca[2*j+1]);
        pa4[j] = make_float4(x.x, x.y, y.x, y.y);
        float2 u = upk2(accb[2*j]), v = upk2(accb[2*j+1]);
        pb4[j] = make_float4(u.x, u.y, v.x, v.y);
    }

    // ---- last block of this group merges the splits (plain sums) ----
    const int g = blockIdx.x + (L_ / ROWSPB) * (h + H_ * b);
    __threadfence();
    if (tid == 0) {
        int prev = atomicAdd(&g_cnt[g], 1);
        sLast = (prev == SPLITS - 1);
    }
    __syncthreads();
    if (!sLast) return;
    __threadfence();

    // 64 threads merge 128 rows x 8 float4 chunks = 1024 items.
    #pragma unroll 1
    for (int it = 0; it < (ROWSPB * 8) / THREADS; it++) {
        int item = it * THREADS + tid;
        int rl = item >> 3;
        int jj = item & 7;
        int r  = ((b * L_ + lbase + rl) * H_ + h);
        float denom = 0.f;
        float4 o = make_float4(0.f, 0.f, 0.f, 0.f);
        #pragma unroll
        for (int sp = 0; sp < SPLITS; sp++) {
            denom += g_l[sp * NR + r];
            float4 a = g_acc[(size_t)(sp * NR + r) * 8 + jj];
            o.x += a.x; o.y += a.y; o.z += a.z; o.w += a.w;
        }
        float inv = 1.0f / denom;
        o.x *= inv; o.y *= inv; o.z *= inv; o.w *= inv;
        ((float4*)O)[(size_t)r * 8 + jj] = o;
    }
    if (tid == 0) g_cnt[g] = 0;   // self-reset for next graph replay
}

extern "C" void kernel_launch(void* const* d_in, const int* in_sizes, int n_in,
                              void* d_out, int out_size) {
    const float* Q = (const float*)d_in[0];
    const float* K = (const float*)d_in[1];
    const float* V = (const float*)d_in[2];
    float* O = (float*)d_out;
    (void)in_sizes; (void)n_in; (void)out_size;
    kprep_kernel<<<B_ * H_, 256>>>(K);
    dim3 grid(L_ / ROWSPB, H_, B_ * SPLITS);   // 16 x 8 x 4 = 512 blocks
    geom_attn_fused<<<grid, THREADS>>>(Q, K, V, O);
}

// round 15
// speedup vs baseline: 1.5317x; 1.5317x over previous
#include <cuda_runtime.h>
#include <cuda_fp16.h>
#include <math_constants.h>

// GeomAttention: B=2, L=S=2048, H=8, E=D=32, fp32.
// Cauchy-Schwarz => relu never fires: score = c*(dot+dot^2) - c*qn2*kn2.
//
// R15: tensor-core path via mma.sync.m16n8k16 f16 with split-precision:
//   QK: dot = qhi*khi + qhi*klo + qlo*khi   (~1e-5 error, enough for dot^2)
//   PV: O   = phi*vhi + phi*vlo + plo*vhi
// Online per-16-key-chunk max (fp16 P requires p<=1), branchless ex2 rescale.
// Warp = 16 rows x full S. K smem pitch 20 words / V^T pitch 36 words give
// bank-conflict-free scalar LDS B-fragments (no ldmatrix). P->A frag is
// register-only. No splits, no merge kernel.

static constexpr int B_ = 2, L_ = 2048, H_ = 8, E_ = 32;
static constexpr int TS = 64;           // keys per tile
static constexpr int NT = L_ / TS;      // 32 tiles
static constexpr int THREADS = 128;     // 4 warps
static constexpr int ROWSPB = 64;       // 16 rows per warp
static constexpr int KP = 20;           // K tile row pitch (u32 words): 20g+c unique mod 32
static constexpr int VP = 36;           // V^T row pitch (u32 words): 4g+c unique mod 32

__device__ float g_kn2[B_ * H_ * L_];   // [(b*H+h)*L + s]

typedef unsigned int u32;

__device__ __forceinline__ float ex2f(float x) {
    float r; asm("ex2.approx.f32 %0, %1;" : "=f"(r) : "f"(x)); return r;
}
__device__ __forceinline__ u32 h2(float lo, float hi) {
    __half2 t = __floats2half2_rn(lo, hi);   // .x (low bits) = first arg
    return *reinterpret_cast<u32*>(&t);
}
__device__ __forceinline__ float2 h2f(u32 v) {
    __half2 t = *reinterpret_cast<__half2*>(&v);
    return make_float2(__low2float(t), __high2float(t));
}
__device__ __forceinline__ void mma_f16(float* c, const u32* a, u32 b0, u32 b1) {
    asm volatile(
        "mma.sync.aligned.m16n8k16.row.col.f32.f16.f16.f32 "
        "{%0,%1,%2,%3},{%4,%5,%6,%7},{%8,%9},{%0,%1,%2,%3};"
        : "+f"(c[0]), "+f"(c[1]), "+f"(c[2]), "+f"(c[3])
        : "r"(a[0]), "r"(a[1]), "r"(a[2]), "r"(a[3]), "r"(b0), "r"(b1));
}

// ---- pre-kernel: per-key |k|^2 ----
__global__ __launch_bounds__(256) void kprep_kernel(const float* __restrict__ K)
{
    const int bh = blockIdx.x;               // 0..B*H-1
    const int b = bh / H_, h = bh % H_;
    const float* kb = K + ((size_t)b * L_ * H_ + h) * E_;
    for (int s = threadIdx.x; s < L_; s += 256) {
        const float4* kp = (const float4*)(kb + (size_t)s * H_ * E_);
        float kn = 0.f;
        #pragma unroll
        for (int j = 0; j < 8; j++) {
            float4 v = kp[j];
            kn += v.x*v.x + v.y*v.y + v.z*v.z + v.w*v.w;
        }
        g_kn2[(size_t)bh * L_ + s] = kn;
    }
}

__global__ __launch_bounds__(THREADS, 3) void geom_attn_mma(
    const float* __restrict__ Q, const float* __restrict__ K,
    const float* __restrict__ V, float* __restrict__ O)
{
    __shared__ u32  sKhi[TS * KP], sKlo[TS * KP];   // [key][elem-pair], pitch 20
    __shared__ u32  sVhi[E_ * VP], sVlo[E_ * VP];   // transposed [elem][key-pair], pitch 36
    __shared__ float sKn2[TS];

    const int tid  = threadIdx.x;
    const int lane = tid & 31, warp = tid >> 5;
    const int g    = lane >> 2, cc = lane & 3;
    const int h    = blockIdx.y, b = blockIdx.z;
    const int rowbase = blockIdx.x * ROWSPB + warp * 16;
    const int row0 = rowbase + g, row1 = row0 + 8;
    const size_t HE = (size_t)H_ * E_;

    const float* qb = Q + ((size_t)b * L_ * H_ + h) * E_;
    const float* kb = K + ((size_t)b * L_ * H_ + h) * E_;
    const float* vb = V + ((size_t)b * L_ * H_ + h) * E_;

    // ---- Q fragments (hi/lo split) + qn2 via quad reduction ----
    u32 qhi[2][4], qlo[2][4];
    float qn0 = 0.f, qn1 = 0.f;
    #pragma unroll
    for (int kc = 0; kc < 2; kc++) {
        float2 e00 = *(const float2*)(qb + (size_t)row0 * HE + kc*16 + 2*cc);
        float2 e01 = *(const float2*)(qb + (size_t)row0 * HE + kc*16 + 8 + 2*cc);
        float2 e10 = *(const float2*)(qb + (size_t)row1 * HE + kc*16 + 2*cc);
        float2 e11 = *(const float2*)(qb + (size_t)row1 * HE + kc*16 + 8 + 2*cc);
        qn0 += e00.x*e00.x + e00.y*e00.y + e01.x*e01.x + e01.y*e01.y;
        qn1 += e10.x*e10.x + e10.y*e10.y + e11.x*e11.x + e11.y*e11.y;
        u32 hx; float2 hf;
        hx = h2(e00.x, e00.y); hf = h2f(hx); qhi[kc][0] = hx; qlo[kc][0] = h2(e00.x-hf.x, e00.y-hf.y);
        hx = h2(e10.x, e10.y); hf = h2f(hx); qhi[kc][1] = hx; qlo[kc][1] = h2(e10.x-hf.x, e10.y-hf.y);
        hx = h2(e01.x, e01.y); hf = h2f(hx); qhi[kc][2] = hx; qlo[kc][2] = h2(e01.x-hf.x, e01.y-hf.y);
        hx = h2(e11.x, e11.y); hf = h2f(hx); qhi[kc][3] = hx; qlo[kc][3] = h2(e11.x-hf.x, e11.y-hf.y);
    }
    qn0 += __shfl_xor_sync(~0u, qn0, 1); qn0 += __shfl_xor_sync(~0u, qn0, 2);
    qn1 += __shfl_xor_sync(~0u, qn1, 1); qn1 += __shfl_xor_sync(~0u, qn1, 2);

    const float c2  = 0.5f * rsqrtf((float)E_) * 1.44269504f;   // log2 domain
    const float cq0 = c2 * qn0, cq1 = c2 * qn1;

    float oacc[16];
    #pragma unroll
    for (int i = 0; i < 16; i++) oacc[i] = 0.f;
    float ls0 = 0.f, ls1 = 0.f, m0 = -1e30f, m1 = -1e30f;
    const float* knb = g_kn2 + (size_t)(b * H_ + h) * L_;

    for (int t = 0; t < NT; t++) {
        __syncthreads();                   // previous tile's compute done
        // ---- load + split K tile, V tile (transposed) ----
        #pragma unroll
        for (int i = 0; i < 4; i++) {
            int lin = tid + i * THREADS;   // 0..511
            int key = lin >> 3, e4 = lin & 7;
            const float4 kv = *(const float4*)(kb + (size_t)(t*TS + key) * HE + e4*4);
            {
                u32 hx = h2(kv.x, kv.y); float2 hf = h2f(hx);
                u32 lx = h2(kv.x - hf.x, kv.y - hf.y);
                u32 hy = h2(kv.z, kv.w); float2 hg = h2f(hy);
                u32 ly = h2(kv.z - hg.x, kv.w - hg.y);
                sKhi[key*KP + e4*2]     = hx;  sKhi[key*KP + e4*2 + 1] = hy;
                sKlo[key*KP + e4*2]     = lx;  sKlo[key*KP + e4*2 + 1] = ly;
            }
            const float4 vv = *(const float4*)(vb + (size_t)(t*TS + key) * HE + e4*4);
            {
                __half* vh = (__half*)sVhi; __half* vl = (__half*)sVlo;
                #pragma unroll
                for (int j = 0; j < 4; j++) {
                    float x = (&vv.x)[j];
                    __half hx = __float2half_rn(x);
                    vh[(e4*4 + j) * (VP*2) + key] = hx;
                    vl[(e4*4 + j) * (VP*2) + key] = __float2half_rn(x - __half2float(hx));
                }
            }
        }
        if (tid < TS) sKn2[tid] = knb[t*TS + tid];
        __syncthreads();

        #pragma unroll 1
        for (int kc = 0; kc < 4; kc++) {   // 16-key chunks
            float sc[2][4];
            #pragma unroll
            for (int hf2 = 0; hf2 < 2; hf2++) {
                const int nb = kc*2 + hf2;
                float d[4] = {0.f, 0.f, 0.f, 0.f};
                #pragma unroll
                for (int qc = 0; qc < 2; qc++) {
                    int base = (nb*8 + g) * KP + qc*8 + cc;
                    u32 bh0 = sKhi[base], bh1 = sKhi[base + 4];
                    u32 bl0 = sKlo[base], bl1 = sKlo[base + 4];
                    mma_f16(d, qhi[qc], bh0, bh1);   // hi*hi
                    mma_f16(d, qhi[qc], bl0, bl1);   // hi*lo
                    mma_f16(d, qlo[qc], bh0, bh1);   // lo*hi
                }
                float2 kn = *(const float2*)&sKn2[nb*8 + 2*cc];
                sc[hf2][0] = fmaf(c2, fmaf(d[0], d[0], d[0]), -cq0 * kn.x);
                sc[hf2][1] = fmaf(c2, fmaf(d[1], d[1], d[1]), -cq0 * kn.y);
                sc[hf2][2] = fmaf(c2, fmaf(d[2], d[2], d[2]), -cq1 * kn.x);
                sc[hf2][3] = fmaf(c2, fmaf(d[3], d[3], d[3]), -cq1 * kn.y);
            }
            // ---- online max over this 16-key chunk (quad = one row pair) ----
            float cm0 = fmaxf(fmaxf(sc[0][0], sc[0][1]), fmaxf(sc[1][0], sc[1][1]));
            float cm1 = fmaxf(fmaxf(sc[0][2], sc[0][3]), fmaxf(sc[1][2], sc[1][3]));
            cm0 = fmaxf(cm0, __shfl_xor_sync(~0u, cm0, 1));
            cm0 = fmaxf(cm0, __shfl_xor_sync(~0u, cm0, 2));
            cm1 = fmaxf(cm1, __shfl_xor_sync(~0u, cm1, 1));
            cm1 = fmaxf(cm1, __shfl_xor_sync(~0u, cm1, 2));
            float mn0 = fmaxf(m0, cm0), mn1 = fmaxf(m1, cm1);
            float r0 = ex2f(m0 - mn0), r1 = ex2f(m1 - mn1);
            m0 = mn0; m1 = mn1; ls0 *= r0; ls1 *= r1;
            #pragma unroll
            for (int of = 0; of < 4; of++) {
                oacc[of*4 + 0] *= r0; oacc[of*4 + 1] *= r0;
                oacc[of*4 + 2] *= r1; oacc[of*4 + 3] *= r1;
            }
            // ---- p = 2^(s-m), build A fragments (hi/lo split) ----
            u32 Ahi[4], Alo[4];
            #pragma unroll
            for (int hf2 = 0; hf2 < 2; hf2++) {
                float p0 = ex2f(sc[hf2][0] - m0), p1 = ex2f(sc[hf2][1] - m0);
                float p2 = ex2f(sc[hf2][2] - m1), p3 = ex2f(sc[hf2][3] - m1);
                ls0 += p0 + p1; ls1 += p2 + p3;
                u32 h01 = h2(p0, p1); float2 f01 = h2f(h01);
                u32 h23 = h2(p2, p3); float2 f23 = h2f(h23);
                Ahi[hf2*2 + 0] = h01;
                Ahi[hf2*2 + 1] = h23;
                Alo[hf2*2 + 0] = h2(p0 - f01.x, p1 - f01.y);
                Alo[hf2*2 + 1] = h2(p2 - f23.x, p3 - f23.y);
            }
            // ---- PV: O += phi*vhi + phi*vlo + plo*vhi ----
            #pragma unroll
            for (int of = 0; of < 4; of++) {
                int base = (of*8 + g) * VP + kc*8 + cc;
                u32 vh0 = sVhi[base], vh1 = sVhi[base + 4];
                u32 vl0 = sVlo[base], vl1 = sVlo[base + 4];
                mma_f16(&oacc[of*4], Ahi, vh0, vh1);
                mma_f16(&oacc[of*4], Ahi, vl0, vl1);
                mma_f16(&oacc[of*4], Alo, vh0, vh1);
            }
        }
    }

    // ---- finalize: quad-reduce ls, normalize, store ----
    ls0 += __shfl_xor_sync(~0u, ls0, 1); ls0 += __shfl_xor_sync(~0u, ls0, 2);
    ls1 += __shfl_xor_sync(~0u, ls1, 1); ls1 += __shfl_xor_sync(~0u, ls1, 2);
    const float inv0 = 1.f / ls0, inv1 = 1.f / ls1;
    float* o0 = O + ((size_t)b * L_ + row0) * HE + h * E_;
    float* o1 = O + ((size_t)b * L_ + row1) * HE + h * E_;
    #pragma unroll
    for (int of = 0; of < 4; of++) {
        *(float2*)(o0 + of*8 + 2*cc) = make_float2(oacc[of*4 + 0] * inv0, oacc[of*4 + 1] * inv0);
        *(float2*)(o1 + of*8 + 2*cc) = make_float2(oacc[of*4 + 2] * inv1, oacc[of*4 + 3] * inv1);
    }
}

extern "C" void kernel_launch(void* const* d_in, const int* in_sizes, int n_in,
                              void* d_out, int out_size) {
    const float* Q = (const float*)d_in[0];
    const float* K = (const float*)d_in[1];
    const float* V = (const float*)d_in[2];
    float* O = (float*)d_out;
    (void)in_sizes; (void)n_in; (void)out_size;
    kprep_kernel<<<B_ * H_, 256>>>(K);
    dim3 grid(L_ / ROWSPB, H_, B_);   // 32 x 8 x 2 = 512 blocks
    geom_attn_mma<<<grid, THREADS>>>(Q, K, V, O);
}

// round 16
// speedup vs baseline: 1.6031x; 1.0466x over previous
#include <cuda_runtime.h>
#include <cuda_fp16.h>

// GeomAttention: B=2, L=S=2048, H=8, E=D=32, fp32.
// Cauchy-Schwarz => relu never fires: score = c*(dot+dot^2) - c*qn2*kn2.
//
// R16: tensor path (mma.sync m16n8k16 f16, split-precision 3-term products)
// with ALL conversion hoisted to a pre-kernel: K stored as interleaved
// (hi,lo) fp16-pair u64 [bh][key][ep]; V stored transposed [bh][elem][keypair].
// Main kernel tiles are pure cp.async.16 copies, double-buffered. Fragment
// loads are conflict-free LDS.64 (pitch 20/36 u64). Per-tile online max.

static constexpr int B_ = 2, L_ = 2048, H_ = 8, E_ = 32;
static constexpr int BH = B_ * H_;
static constexpr int TS = 64;           // keys per tile
static constexpr int NT = L_ / TS;      // 32 tiles
static constexpr int THREADS = 128;     // 4 warps
static constexpr int ROWSPB = 64;       // 16 rows per warp
static constexpr int KPD = 20;          // K row pitch (u64): 16 data + 4 pad
static constexpr int VPD = 36;          // V^T row pitch (u64): 32 data + 4 pad

typedef unsigned int u32;
typedef unsigned long long u64;

__device__ float g_kn2[BH * L_];
__device__ __align__(16) u32 gK[BH * L_ * 32];          // [bh][key][ep]{hi,lo}
__device__ __align__(16) u32 gV[BH * E_ * (L_ / 2) * 2]; // [bh][e][kp]{hi,lo}

__device__ __forceinline__ float ex2f(float x) {
    float r; asm("ex2.approx.f32 %0, %1;" : "=f"(r) : "f"(x)); return r;
}
__device__ __forceinline__ u32 h2(float lo, float hi) {
    __half2 t = __floats2half2_rn(lo, hi);
    return *reinterpret_cast<u32*>(&t);
}
__device__ __forceinline__ float2 h2f(u32 v) {
    __half2 t = *reinterpret_cast<__half2*>(&v);
    return make_float2(__low2float(t), __high2float(t));
}
__device__ __forceinline__ void mma_f16(float* c, const u32* a, u32 b0, u32 b1) {
    asm volatile(
        "mma.sync.aligned.m16n8k16.row.col.f32.f16.f16.f32 "
        "{%0,%1,%2,%3},{%4,%5,%6,%7},{%8,%9},{%0,%1,%2,%3};"
        : "+f"(c[0]), "+f"(c[1]), "+f"(c[2]), "+f"(c[3])
        : "r"(a[0]), "r"(a[1]), "r"(a[2]), "r"(a[3]), "r"(b0), "r"(b1));
}
__device__ __forceinline__ u32 s2u(const void* p) {
    return (u32)__cvta_generic_to_shared(p);
}
__device__ __forceinline__ void cpa16(u32 dst, const void* src) {
    asm volatile("cp.async.cg.shared.global [%0], [%1], 16;" :: "r"(dst), "l"(src));
}
#define CPA_COMMIT() asm volatile("cp.async.commit_group;" ::: "memory")
#define CPA_WAIT(n)  asm volatile("cp.async.wait_group %0;" :: "n"(n) : "memory")

// ---- pre-kernel: split/convert K & V once; kn2 ----
__global__ __launch_bounds__(256) void kprep_kernel(
    const float* __restrict__ K, const float* __restrict__ V)
{
    const int bh = blockIdx.x;               // 0..BH-1
    const int b = bh / H_, h = bh % H_;
    const float* kb = K + ((size_t)b * L_ * H_ + h) * E_;
    const float* vb = V + ((size_t)b * L_ * H_ + h) * E_;

    // K: per key, 16 interleaved (hi,lo) pairs; also kn2
    for (int s = threadIdx.x; s < L_; s += 256) {
        const float4* kp = (const float4*)(kb + (size_t)s * H_ * E_);
        u32* dst = gK + ((size_t)bh * L_ + s) * 32;
        float kn = 0.f;
        #pragma unroll
        for (int j = 0; j < 8; j++) {
            float4 v = kp[j];
            kn += v.x*v.x + v.y*v.y + v.z*v.z + v.w*v.w;
            u32 h0 = h2(v.x, v.y); float2 f0 = h2f(h0);
            u32 h1 = h2(v.z, v.w); float2 f1 = h2f(h1);
            dst[j*4 + 0] = h0; dst[j*4 + 1] = h2(v.x - f0.x, v.y - f0.y);
            dst[j*4 + 2] = h1; dst[j*4 + 3] = h2(v.z - f1.x, v.w - f1.y);
        }
        g_kn2[(size_t)bh * L_ + s] = kn;
    }
    // V: transposed, per elem row, key-pair (hi,lo) u64s
    for (int sp = threadIdx.x; sp < L_ / 2; sp += 256) {
        const float4* v0 = (const float4*)(vb + (size_t)(2*sp)     * H_ * E_);
        const float4* v1 = (const float4*)(vb + (size_t)(2*sp + 1) * H_ * E_);
        #pragma unroll
        for (int j = 0; j < 8; j++) {
            float4 a = v0[j], c = v1[j];
            float pe[4][2] = {{a.x,c.x},{a.y,c.y},{a.z,c.z},{a.w,c.w}};
            #pragma unroll
            for (int e4 = 0; e4 < 4; e4++) {
                int e = j*4 + e4;
                u32 hi = h2(pe[e4][0], pe[e4][1]); float2 f = h2f(hi);
                u32 lo = h2(pe[e4][0] - f.x, pe[e4][1] - f.y);
                u32* d = gV + (((size_t)bh * E_ + e) * (L_/2) + sp) * 2;
                d[0] = hi; d[1] = lo;
            }
        }
    }
}

__global__ __launch_bounds__(THREADS, 3) void geom_attn_mma(
    const float* __restrict__ Q, float* __restrict__ O)
{
    __shared__ __align__(16) u32 sK[2][TS * KPD * 2];   // 2 x 10 KB
    __shared__ __align__(16) u32 sV[2][E_ * VPD * 2];   // 2 x 9 KB

    const int tid  = threadIdx.x;
    const int lane = tid & 31, warp = tid >> 5;
    const int g    = lane >> 2, cc = lane & 3;
    const int h    = blockIdx.y, b = blockIdx.z;
    const int bh   = b * H_ + h;
    const int row0 = blockIdx.x * ROWSPB + warp * 16 + g;
    const int row1 = row0 + 8;
    const size_t HE = (size_t)H_ * E_;

    const u32* srcK = gK + (size_t)bh * L_ * 32;
    const float* knb = g_kn2 + (size_t)bh * L_;

    // ---- tile loader: pure cp.async copies ----
    auto load_tile = [&](int t, int buf) {
        const u32* kt = srcK + (size_t)t * TS * 32;
        #pragma unroll
        for (int i = 0; i < 4; i++) {
            int lin = tid + i * THREADS;        // 0..511
            int key = lin >> 3, gr = lin & 7;
            cpa16(s2u(&sK[buf][key * (KPD*2) + gr*4]), kt + key*32 + gr*4);
        }
        #pragma unroll
        for (int i = 0; i < 4; i++) {
            int lin = tid + i * THREADS;
            int e = lin >> 4, gr = lin & 15;
            cpa16(s2u(&sV[buf][e * (VPD*2) + gr*4]),
                  gV + (((size_t)bh * E_ + e) * (L_/2) + t*(TS/2)) * 2 + gr*4);
        }
        CPA_COMMIT();
    };
    load_tile(0, 0);

    // ---- Q fragments (hi/lo split) + qn2 (overlaps cp.async) ----
    const float* qb = Q + ((size_t)b * L_ * H_ + h) * E_;
    u32 qhi[2][4], qlo[2][4];
    float qn0 = 0.f, qn1 = 0.f;
    #pragma unroll
    for (int kc = 0; kc < 2; kc++) {
        float2 e00 = *(const float2*)(qb + (size_t)row0 * HE + kc*16 + 2*cc);
        float2 e01 = *(const float2*)(qb + (size_t)row0 * HE + kc*16 + 8 + 2*cc);
        float2 e10 = *(const float2*)(qb + (size_t)row1 * HE + kc*16 + 2*cc);
        float2 e11 = *(const float2*)(qb + (size_t)row1 * HE + kc*16 + 8 + 2*cc);
        qn0 += e00.x*e00.x + e00.y*e00.y + e01.x*e01.x + e01.y*e01.y;
        qn1 += e10.x*e10.x + e10.y*e10.y + e11.x*e11.x + e11.y*e11.y;
        u32 hx; float2 hf;
        hx = h2(e00.x, e00.y); hf = h2f(hx); qhi[kc][0] = hx; qlo[kc][0] = h2(e00.x-hf.x, e00.y-hf.y);
        hx = h2(e10.x, e10.y); hf = h2f(hx); qhi[kc][1] = hx; qlo[kc][1] = h2(e10.x-hf.x, e10.y-hf.y);
        hx = h2(e01.x, e01.y); hf = h2f(hx); qhi[kc][2] = hx; qlo[kc][2] = h2(e01.x-hf.x, e01.y-hf.y);
        hx = h2(e11.x, e11.y); hf = h2f(hx); qhi[kc][3] = hx; qlo[kc][3] = h2(e11.x-hf.x, e11.y-hf.y);
    }
    qn0 += __shfl_xor_sync(~0u, qn0, 1); qn0 += __shfl_xor_sync(~0u, qn0, 2);
    qn1 += __shfl_xor_sync(~0u, qn1, 1); qn1 += __shfl_xor_sync(~0u, qn1, 2);

    const float c2  = 0.5f * rsqrtf((float)E_) * 1.44269504f;   // log2 domain
    const float cq0 = c2 * qn0, cq1 = c2 * qn1;

    float oacc[16];
    #pragma unroll
    for (int i = 0; i < 16; i++) oacc[i] = 0.f;
    float ls0 = 0.f, ls1 = 0.f, m0 = -1e30f, m1 = -1e30f;

    for (int t = 0; t < NT; t++) {
        const int buf = t & 1;
        if (t + 1 < NT) { load_tile(t + 1, buf ^ 1); CPA_WAIT(1); }
        else           { CPA_WAIT(0); }
        __syncthreads();                   // tile t visible to all warps

        // prefetch kn2 for this tile (L1/L2-resident)
        float2 knr[8];
        #pragma unroll
        for (int nb = 0; nb < 8; nb++)
            knr[nb] = *(const float2*)&knb[t*TS + nb*8 + 2*cc];

        const u64* kb64 = (const u64*)&sK[buf][0];
        const u64* vb64 = (const u64*)&sV[buf][0];

        // ---- QK scores for the whole 64-key tile ----
        float sc[8][4];
        #pragma unroll
        for (int nb = 0; nb < 8; nb++) {
            float d[4] = {0.f, 0.f, 0.f, 0.f};
            #pragma unroll
            for (int qc = 0; qc < 2; qc++) {
                u64 w0 = kb64[(nb*8 + g) * KPD + qc*8 + cc];
                u64 w1 = kb64[(nb*8 + g) * KPD + qc*8 + cc + 4];
                u32 bh0 = (u32)w0, bl0 = (u32)(w0 >> 32);
                u32 bh1 = (u32)w1, bl1 = (u32)(w1 >> 32);
                mma_f16(d, qhi[qc], bh0, bh1);   // hi*hi
                mma_f16(d, qhi[qc], bl0, bl1);   // hi*lo
                mma_f16(d, qlo[qc], bh0, bh1);   // lo*hi
            }
            sc[nb][0] = fmaf(c2, fmaf(d[0], d[0], d[0]), -cq0 * knr[nb].x);
            sc[nb][1] = fmaf(c2, fmaf(d[1], d[1], d[1]), -cq0 * knr[nb].y);
            sc[nb][2] = fmaf(c2, fmaf(d[2], d[2], d[2]), -cq1 * knr[nb].x);
            sc[nb][3] = fmaf(c2, fmaf(d[3], d[3], d[3]), -cq1 * knr[nb].y);
        }

        // ---- per-tile online max + rescale ----
        float cm0 = sc[0][0], cm1 = sc[0][2];
        #pragma unroll
        for (int nb = 0; nb < 8; nb++) {
            cm0 = fmaxf(cm0, fmaxf(sc[nb][0], sc[nb][1]));
            cm1 = fmaxf(cm1, fmaxf(sc[nb][2], sc[nb][3]));
        }
        cm0 = fmaxf(cm0, __shfl_xor_sync(~0u, cm0, 1));
        cm0 = fmaxf(cm0, __shfl_xor_sync(~0u, cm0, 2));
        cm1 = fmaxf(cm1, __shfl_xor_sync(~0u, cm1, 1));
        cm1 = fmaxf(cm1, __shfl_xor_sync(~0u, cm1, 2));
        float mn0 = fmaxf(m0, cm0), mn1 = fmaxf(m1, cm1);
        float r0 = ex2f(m0 - mn0), r1 = ex2f(m1 - mn1);
        m0 = mn0; m1 = mn1; ls0 *= r0; ls1 *= r1;
        #pragma unroll
        for (int of = 0; of < 4; of++) {
            oacc[of*4 + 0] *= r0; oacc[of*4 + 1] *= r0;
            oacc[of*4 + 2] *= r1; oacc[of*4 + 3] *= r1;
        }

        // ---- PV per 16-key chunk ----
        #pragma unroll
        for (int kc = 0; kc < 4; kc++) {
            u32 Ahi[4], Alo[4];
            #pragma unroll
            for (int hf2 = 0; hf2 < 2; hf2++) {
                const int nb = kc*2 + hf2;
                float p0 = ex2f(sc[nb][0] - m0), p1 = ex2f(sc[nb][1] - m0);
                float p2 = ex2f(sc[nb][2] - m1), p3 = ex2f(sc[nb][3] - m1);
                ls0 += p0 + p1; ls1 += p2 + p3;
                u32 h01 = h2(p0, p1); float2 f01 = h2f(h01);
                u32 h23 = h2(p2, p3); float2 f23 = h2f(h23);
                Ahi[hf2*2 + 0] = h01;
                Ahi[hf2*2 + 1] = h23;
                Alo[hf2*2 + 0] = h2(p0 - f01.x, p1 - f01.y);
                Alo[hf2*2 + 1] = h2(p2 - f23.x, p3 - f23.y);
            }
            #pragma unroll
            for (int of = 0; of < 4; of++) {
                u64 w0 = vb64[(of*8 + g) * VPD + kc*8 + cc];
                u64 w1 = vb64[(of*8 + g) * VPD + kc*8 + cc + 4];
                u32 vh0 = (u32)w0, vl0 = (u32)(w0 >> 32);
                u32 vh1 = (u32)w1, vl1 = (u32)(w1 >> 32);
                mma_f16(&oacc[of*4], Ahi, vh0, vh1);
                mma_f16(&oacc[of*4], Ahi, vl0, vl1);
                mma_f16(&oacc[of*4], Alo, vh0, vh1);
            }
        }
        __syncthreads();                   // all warps done before buf is reloaded
    }

    // ---- finalize: quad-reduce ls, normalize, store ----
    ls0 += __shfl_xor_sync(~0u, ls0, 1); ls0 += __shfl_xor_sync(~0u, ls0, 2);
    ls1 += __shfl_xor_sync(~0u, ls1, 1); ls1 += __shfl_xor_sync(~0u, ls1, 2);
    const float inv0 = 1.f / ls0, inv1 = 1.f / ls1;
    float* o0 = O + ((size_t)b * L_ + row0) * HE + h * E_;
    float* o1 = O + ((size_t)b * L_ + row1) * HE + h * E_;
    #pragma unroll
    for (int of = 0; of < 4; of++) {
        *(float2*)(o0 + of*8 + 2*cc) = make_float2(oacc[of*4 + 0] * inv0, oacc[of*4 + 1] * inv0);
        *(float2*)(o1 + of*8 + 2*cc) = make_float2(oacc[of*4 + 2] * inv1, oacc[of*4 + 3] * inv1);
    }
}

extern "C" void kernel_launch(void* const* d_in, const int* in_sizes, int n_in,
                              void* d_out, int out_size) {
    const float* Q = (const float*)d_in[0];
    const float* K = (const float*)d_in[1];
    const float* V = (const float*)d_in[2];
    float* O = (float*)d_out;
    (void)in_sizes; (void)n_in; (void)out_size;
    kprep_kernel<<<BH, 256>>>(K, V);
    dim3 grid(L_ / ROWSPB, H_, B_);   // 32 x 8 x 2 = 512 blocks
    geom_attn_mma<<<grid, THREADS>>>(Q, O);
}

// round 17
// speedup vs baseline: 2.0253x; 1.2633x over previous
#include <cuda_runtime.h>
#include <cuda_fp16.h>

// GeomAttention: B=2, L=S=2048, H=8, E=D=32, fp32.
// Cauchy-Schwarz => relu never fires: score = c*(dot+dot^2) - c*qn2*kn2.
//
// R17: R16 (tensor mma path, pre-converted split-fp16 K/V, cp.async double
// buffering) with: (1) pre-kernel spread over 256 blocks (was 16 -> ~30us),
// (2) uint2 fragment loads (no u64 SHF extraction -> alu pipe),
// (3) launch_bounds(128,4) for 4 blocks/SM.

static constexpr int B_ = 2, L_ = 2048, H_ = 8, E_ = 32;
static constexpr int BH = B_ * H_;
static constexpr int TS = 64;           // keys per tile
static constexpr int NT = L_ / TS;      // 32 tiles
static constexpr int THREADS = 128;     // 4 warps
static constexpr int ROWSPB = 64;       // 16 rows per warp
static constexpr int KPD = 20;          // K row pitch (uint2): 16 data + 4 pad
static constexpr int VPD = 36;          // V^T row pitch (uint2): 32 data + 4 pad

typedef unsigned int u32;

__device__ float g_kn2[BH * L_];
__device__ __align__(16) u32 gK[BH * L_ * 32];           // [bh][key][ep]{hi,lo}
__device__ __align__(16) u32 gV[BH * E_ * (L_ / 2) * 2]; // [bh][e][kp]{hi,lo}

__device__ __forceinline__ float ex2f(float x) {
    float r; asm("ex2.approx.f32 %0, %1;" : "=f"(r) : "f"(x)); return r;
}
__device__ __forceinline__ u32 h2(float lo, float hi) {
    __half2 t = __floats2half2_rn(lo, hi);
    return *reinterpret_cast<u32*>(&t);
}
__device__ __forceinline__ float2 h2f(u32 v) {
    __half2 t = *reinterpret_cast<__half2*>(&v);
    return make_float2(__low2float(t), __high2float(t));
}
__device__ __forceinline__ void mma_f16(float* c, const u32* a, u32 b0, u32 b1) {
    asm volatile(
        "mma.sync.aligned.m16n8k16.row.col.f32.f16.f16.f32 "
        "{%0,%1,%2,%3},{%4,%5,%6,%7},{%8,%9},{%0,%1,%2,%3};"
        : "+f"(c[0]), "+f"(c[1]), "+f"(c[2]), "+f"(c[3])
        : "r"(a[0]), "r"(a[1]), "r"(a[2]), "r"(a[3]), "r"(b0), "r"(b1));
}
__device__ __forceinline__ u32 s2u(const void* p) {
    return (u32)__cvta_generic_to_shared(p);
}
__device__ __forceinline__ void cpa16(u32 dst, const void* src) {
    asm volatile("cp.async.cg.shared.global [%0], [%1], 16;" :: "r"(dst), "l"(src));
}
#define CPA_COMMIT() asm volatile("cp.async.commit_group;" ::: "memory")
#define CPA_WAIT(n)  asm volatile("cp.async.wait_group %0;" :: "n"(n) : "memory")

// ---- pre-kernel: split/convert K & V once; kn2. 256 blocks (BH x 16). ----
__global__ __launch_bounds__(256) void kprep_kernel(
    const float* __restrict__ K, const float* __restrict__ V)
{
    const int bh    = blockIdx.x;            // 0..BH-1
    const int chunk = blockIdx.y;            // 0..15 (128 keys each)
    const int b = bh / H_, h = bh % H_;
    const float* kb = K + ((size_t)b * L_ * H_ + h) * E_;
    const float* vb = V + ((size_t)b * L_ * H_ + h) * E_;
    const int t = threadIdx.x;

    // K: 2 threads per key (each converts 16 of 32 elems); kn2 via pair shfl.
    {
        const int key  = chunk * 128 + (t >> 1);
        const int half = t & 1;
        const float4* kp = (const float4*)(kb + (size_t)key * H_ * E_) + half * 4;
        u32* dst = gK + ((size_t)bh * L_ + key) * 32 + half * 16;
        float kn = 0.f;
        #pragma unroll
        for (int j = 0; j < 4; j++) {
            float4 v = kp[j];
            kn += v.x*v.x + v.y*v.y + v.z*v.z + v.w*v.w;
            u32 h0 = h2(v.x, v.y); float2 f0 = h2f(h0);
            u32 h1 = h2(v.z, v.w); float2 f1 = h2f(h1);
            dst[j*4 + 0] = h0; dst[j*4 + 1] = h2(v.x - f0.x, v.y - f0.y);
            dst[j*4 + 2] = h1; dst[j*4 + 3] = h2(v.z - f1.x, v.w - f1.y);
        }
        kn += __shfl_xor_sync(~0u, kn, 1);
        if (half == 0) g_kn2[(size_t)bh * L_ + key] = kn;
    }
    // V: transposed; 32 elems x 64 key-pairs per chunk = 2048 items.
    #pragma unroll
    for (int i = 0; i < 8; i++) {
        int lin = t + i * 256;               // 0..2047
        int e = lin >> 6, spl = lin & 63;
        int sp = chunk * 64 + spl;
        float x0 = vb[(size_t)(2*sp)     * H_ * E_ + e];
        float x1 = vb[(size_t)(2*sp + 1) * H_ * E_ + e];
        u32 hi = h2(x0, x1); float2 f = h2f(hi);
        u32 lo = h2(x0 - f.x, x1 - f.y);
        u32* d = gV + (((size_t)bh * E_ + e) * (L_/2) + sp) * 2;
        d[0] = hi; d[1] = lo;
    }
}

__global__ __launch_bounds__(THREADS, 4) void geom_attn_mma(
    const float* __restrict__ Q, float* __restrict__ O)
{
    __shared__ __align__(16) u32 sK[2][TS * KPD * 2];   // 2 x 10 KB
    __shared__ __align__(16) u32 sV[2][E_ * VPD * 2];   // 2 x 9 KB

    const int tid  = threadIdx.x;
    const int lane = tid & 31, warp = tid >> 5;
    const int g    = lane >> 2, cc = lane & 3;
    const int h    = blockIdx.y, b = blockIdx.z;
    const int bh   = b * H_ + h;
    const int row0 = blockIdx.x * ROWSPB + warp * 16 + g;
    const int row1 = row0 + 8;
    const size_t HE = (size_t)H_ * E_;

    const u32* srcK = gK + (size_t)bh * L_ * 32;
    const float* knb = g_kn2 + (size_t)bh * L_;

    auto load_tile = [&](int t, int buf) {
        const u32* kt = srcK + (size_t)t * TS * 32;
        #pragma unroll
        for (int i = 0; i < 4; i++) {
            int lin = tid + i * THREADS;        // 0..511
            int key = lin >> 3, gr = lin & 7;
            cpa16(s2u(&sK[buf][key * (KPD*2) + gr*4]), kt + key*32 + gr*4);
        }
        #pragma unroll
        for (int i = 0; i < 4; i++) {
            int lin = tid + i * THREADS;
            int e = lin >> 4, gr = lin & 15;
            cpa16(s2u(&sV[buf][e * (VPD*2) + gr*4]),
                  gV + (((size_t)bh * E_ + e) * (L_/2) + t*(TS/2)) * 2 + gr*4);
        }
        CPA_COMMIT();
    };
    load_tile(0, 0);

    // ---- Q fragments (hi/lo split) + qn2 (overlaps cp.async) ----
    const float* qb = Q + ((size_t)b * L_ * H_ + h) * E_;
    u32 qhi[2][4], qlo[2][4];
    float qn0 = 0.f, qn1 = 0.f;
    #pragma unroll
    for (int kc = 0; kc < 2; kc++) {
        float2 e00 = *(const float2*)(qb + (size_t)row0 * HE + kc*16 + 2*cc);
        float2 e01 = *(const float2*)(qb + (size_t)row0 * HE + kc*16 + 8 + 2*cc);
        float2 e10 = *(const float2*)(qb + (size_t)row1 * HE + kc*16 + 2*cc);
        float2 e11 = *(const float2*)(qb + (size_t)row1 * HE + kc*16 + 8 + 2*cc);
        qn0 += e00.x*e00.x + e00.y*e00.y + e01.x*e01.x + e01.y*e01.y;
        qn1 += e10.x*e10.x + e10.y*e10.y + e11.x*e11.x + e11.y*e11.y;
        u32 hx; float2 hf;
        hx = h2(e00.x, e00.y); hf = h2f(hx); qhi[kc][0] = hx; qlo[kc][0] = h2(e00.x-hf.x, e00.y-hf.y);
        hx = h2(e10.x, e10.y); hf = h2f(hx); qhi[kc][1] = hx; qlo[kc][1] = h2(e10.x-hf.x, e10.y-hf.y);
        hx = h2(e01.x, e01.y); hf = h2f(hx); qhi[kc][2] = hx; qlo[kc][2] = h2(e01.x-hf.x, e01.y-hf.y);
        hx = h2(e11.x, e11.y); hf = h2f(hx); qhi[kc][3] = hx; qlo[kc][3] = h2(e11.x-hf.x, e11.y-hf.y);
    }
    qn0 += __shfl_xor_sync(~0u, qn0, 1); qn0 += __shfl_xor_sync(~0u, qn0, 2);
    qn1 += __shfl_xor_sync(~0u, qn1, 1); qn1 += __shfl_xor_sync(~0u, qn1, 2);

    const float c2  = 0.5f * rsqrtf((float)E_) * 1.44269504f;   // log2 domain
    const float cq0 = c2 * qn0, cq1 = c2 * qn1;

    float oacc[16];
    #pragma unroll
    for (int i = 0; i < 16; i++) oacc[i] = 0.f;
    float ls0 = 0.f, ls1 = 0.f, m0 = -1e30f, m1 = -1e30f;

    for (int t = 0; t < NT; t++) {
        const int buf = t & 1;
        if (t + 1 < NT) { load_tile(t + 1, buf ^ 1); CPA_WAIT(1); }
        else           { CPA_WAIT(0); }
        __syncthreads();                   // tile t visible to all warps

        float2 knr[8];
        #pragma unroll
        for (int nb = 0; nb < 8; nb++)
            knr[nb] = *(const float2*)&knb[t*TS + nb*8 + 2*cc];

        const uint2* kb2 = (const uint2*)&sK[buf][0];
        const uint2* vb2 = (const uint2*)&sV[buf][0];

        // ---- QK scores for the whole 64-key tile ----
        float sc[8][4];
        #pragma unroll
        for (int nb = 0; nb < 8; nb++) {
            float d[4] = {0.f, 0.f, 0.f, 0.f};
            #pragma unroll
            for (int qc = 0; qc < 2; qc++) {
                uint2 w0 = kb2[(nb*8 + g) * KPD + qc*8 + cc];
                uint2 w1 = kb2[(nb*8 + g) * KPD + qc*8 + cc + 4];
                mma_f16(d, qhi[qc], w0.x, w1.x);   // hi*hi
                mma_f16(d, qhi[qc], w0.y, w1.y);   // hi*lo
                mma_f16(d, qlo[qc], w0.x, w1.x);   // lo*hi
            }
            sc[nb][0] = fmaf(c2, fmaf(d[0], d[0], d[0]), -cq0 * knr[nb].x);
            sc[nb][1] = fmaf(c2, fmaf(d[1], d[1], d[1]), -cq0 * knr[nb].y);
            sc[nb][2] = fmaf(c2, fmaf(d[2], d[2], d[2]), -cq1 * knr[nb].x);
            sc[nb][3] = fmaf(c2, fmaf(d[3], d[3], d[3]), -cq1 * knr[nb].y);
        }

        // ---- per-tile online max + rescale ----
        float cm0 = sc[0][0], cm1 = sc[0][2];
        #pragma unroll
        for (int nb = 0; nb < 8; nb++) {
            cm0 = fmaxf(cm0, fmaxf(sc[nb][0], sc[nb][1]));
            cm1 = fmaxf(cm1, fmaxf(sc[nb][2], sc[nb][3]));
        }
        cm0 = fmaxf(cm0, __shfl_xor_sync(~0u, cm0, 1));
        cm0 = fmaxf(cm0, __shfl_xor_sync(~0u, cm0, 2));
        cm1 = fmaxf(cm1, __shfl_xor_sync(~0u, cm1, 1));
        cm1 = fmaxf(cm1, __shfl_xor_sync(~0u, cm1, 2));
        float mn0 = fmaxf(m0, cm0), mn1 = fmaxf(m1, cm1);
        float r0 = ex2f(m0 - mn0), r1 = ex2f(m1 - mn1);
        m0 = mn0; m1 = mn1; ls0 *= r0; ls1 *= r1;
        #pragma unroll
        for (int of = 0; of < 4; of++) {
            oacc[of*4 + 0] *= r0; oacc[of*4 + 1] *= r0;
            oacc[of*4 + 2] *= r1; oacc[of*4 + 3] *= r1;
        }

        // ---- PV per 16-key chunk ----
        #pragma unroll
        for (int kc = 0; kc < 4; kc++) {
            u32 Ahi[4], Alo[4];
            #pragma unroll
            for (int hf2 = 0; hf2 < 2; hf2++) {
                const int nb = kc*2 + hf2;
                float p0 = ex2f(sc[nb][0] - m0), p1 = ex2f(sc[nb][1] - m0);
                float p2 = ex2f(sc[nb][2] - m1), p3 = ex2f(sc[nb][3] - m1);
                ls0 += p0 + p1; ls1 += p2 + p3;
                u32 h01 = h2(p0, p1); float2 f01 = h2f(h01);
                u32 h23 = h2(p2, p3); float2 f23 = h2f(h23);
                Ahi[hf2*2 + 0] = h01;
                Ahi[hf2*2 + 1] = h23;
                Alo[hf2*2 + 0] = h2(p0 - f01.x, p1 - f01.y);
                Alo[hf2*2 + 1] = h2(p2 - f23.x, p3 - f23.y);
            }
            #pragma unroll
            for (int of = 0; of < 4; of++) {
                uint2 w0 = vb2[(of*8 + g) * VPD + kc*8 + cc];
                uint2 w1 = vb2[(of*8 + g) * VPD + kc*8 + cc + 4];
                mma_f16(&oacc[of*4], Ahi, w0.x, w1.x);
                mma_f16(&oacc[of*4], Ahi, w0.y, w1.y);
                mma_f16(&oacc[of*4], Alo, w0.x, w1.x);
            }
        }
        __syncthreads();                   // all warps done before buf reload
    }

    // ---- finalize: quad-reduce ls, normalize, store ----
    ls0 += __shfl_xor_sync(~0u, ls0, 1); ls0 += __shfl_xor_sync(~0u, ls0, 2);
    ls1 += __shfl_xor_sync(~0u, ls1, 1); ls1 += __shfl_xor_sync(~0u, ls1, 2);
    const float inv0 = 1.f / ls0, inv1 = 1.f / ls1;
    float* o0 = O + ((size_t)b * L_ + row0) * HE + h * E_;
    float* o1 = O + ((size_t)b * L_ + row1) * HE + h * E_;
    #pragma unroll
    for (int of = 0; of < 4; of++) {
        *(float2*)(o0 + of*8 + 2*cc) = make_float2(oacc[of*4 + 0] * inv0, oacc[of*4 + 1] * inv0);
        *(float2*)(o1 + of*8 + 2*cc) = make_float2(oacc[of*4 + 2] * inv1, oacc[of*4 + 3] * inv1);
    }
}

extern "C" void kernel_launch(void* const* d_in, const int* in_sizes, int n_in,
                              void* d_out, int out_size) {
    const float* Q = (const float*)d_in[0];
    const float* K = (const float*)d_in[1];
    const float* V = (const float*)d_in[2];
    float* O = (float*)d_out;
    (void)in_sizes; (void)n_in; (void)out_size;
    dim3 pgrid(BH, 16);
    kprep_kernel<<<pgrid, 256>>>(K, V);
    dim3 grid(L_ / ROWSPB, H_, B_);   // 32 x 8 x 2 = 512 blocks
    geom_attn_mma<<<grid, THREADS>>>(Q, O);
}